// round 10
// baseline (speedup 1.0000x reference)
#include <cuda_runtime.h>
#include <stdint.h>

#define BATCH 16
#define Hdim 1024
#define Wdim 1024
#define NPB (Hdim*Wdim)
#define KTHR 104857
#define TOPK 5
#define CAND_CAP 65536

#define TX 128
#define TY 32
#define HALO 4
#define INW (TX + 2*HALO)    /* 136 */
#define INH (TY + 2*HALO)    /* 40  */
#define PIN 136
#define PRM 128
#define CBUF 256
#define WCAP 88              /* per-warp band segment: mu~47, sigma~6.5 */

#define PRE_L2 766u            /* (fordu(v)>>22) for v in [1.0,1.5) */

/* ------------ scratch (zero-init at load; re-zeroed every run) ------------ */
__device__ unsigned long long g_cand[BATCH][CAND_CAP];
__device__ unsigned int       g_cand_cnt[BATCH];
__device__ unsigned int       g_cntS[BATCH];
__device__ unsigned int       g_ctrC[BATCH][32];
__device__ float              g_band[BATCH][NPB];
__device__ unsigned int       g_band_cnt[BATCH];
__device__ float              g_inbin[BATCH][NPB];
__device__ unsigned int       g_inbin_cnt[BATCH];

__device__ __forceinline__ unsigned int fordu(float f) {
    unsigned int u = __float_as_uint(f);
    return u ^ (unsigned int)(((int)u >> 31) | (int)0x80000000);
}
__device__ __forceinline__ float fordu_inv(unsigned int v) {
    unsigned int u = (v & 0x80000000u) ? (v ^ 0x80000000u) : ~v;
    return __uint_as_float(u);
}
__device__ __forceinline__ unsigned long long umax64(unsigned long long a, unsigned long long b) {
    return a > b ? a : b;
}
#define NEG_INF __int_as_float(0xff800000)

/* 32-bin quantile select: returns sel or -1 */
__device__ __forceinline__ int select32(int b, unsigned int* remOut) {
    unsigned int cum = g_cntS[b];
    for (int j = 31; j >= 0; j--) {
        unsigned int c = g_ctrC[b][j];
        if (cum < (unsigned)KTHR && (unsigned)KTHR <= cum + c) {
            *remOut = (unsigned)KTHR - cum;
            return j;
        }
        cum += c;
    }
    return -1;
}

/* --------- K1: max filter + counting + band collect + peak candidates ----- */
__global__ __launch_bounds__(256) void k1_main(const float* __restrict__ in) {
    __shared__ __align__(16) float s_in[INH * PIN];
    __shared__ __align__(16) float s_rm[INH * PRM];
    __shared__ __align__(16) char  s_u[8 * WCAP * 4];   /* >= CBUF*8 */
    __shared__ unsigned int s_ccnt, s_cbase, s_cn;
    __shared__ unsigned int s_bbase;
    __shared__ unsigned int s_wb[8];
    __shared__ unsigned int s_pref8[8];
    __shared__ unsigned int s_c32[32];
    __shared__ unsigned int s_red[8];

    float* s_band = (float*)s_u;
    unsigned long long* s_cbuf = (unsigned long long*)s_u;

    const int b   = blockIdx.z;
    const int tx0 = blockIdx.x * TX;
    const int ty0 = blockIdx.y * TY;
    const float* base = in + (size_t)b * NPB;
    const int tid  = threadIdx.x;
    const int lane = tid & 31;
    const int wid  = tid >> 5;

    if (tid == 0) s_ccnt = 0u;
    if (tid < 8)  s_wb[tid] = 0u;
    if (tid < 32) s_c32[tid] = 0u;

    /* ---------------- load tile + halo ---------------- */
    const bool interior = (blockIdx.x > 0) && (blockIdx.x < (Wdim/TX - 1)) &&
                          (blockIdx.y > 0) && (blockIdx.y < (Hdim/TY - 1));
    if (interior) {
        const float4* gbase = (const float4*)(base + (size_t)(ty0 - HALO) * Wdim + (tx0 - HALO));
        #pragma unroll
        for (int ri = 0; ri < 5; ri++) {
            int r = wid + ri * 8;
            const float4* grow = gbase + (size_t)r * (Wdim / 4);
            float4* srow = (float4*)&s_in[r * PIN];
            srow[lane] = grow[lane];
            if (lane < 2) srow[32 + lane] = grow[32 + lane];
        }
    } else {
        #pragma unroll
        for (int ri = 0; ri < 5; ri++) {
            int r = wid + ri * 8;
            int gy = ty0 + r - HALO;
            bool rowin = (unsigned)gy < (unsigned)Hdim;
            #pragma unroll
            for (int ci = 0; ci < 5; ci++) {
                int c = lane + ci * 32;
                if (c < INW) {
                    int gx = tx0 + c - HALO;
                    float v = NEG_INF;
                    if (rowin && (unsigned)gx < (unsigned)Wdim) v = base[gy * Wdim + gx];
                    s_in[r * PIN + c] = v;
                }
            }
        }
    }
    __syncthreads();

    /* -------- hpass: warp-per-row vHGW 9-max + lean counting -------------- */
    unsigned int myS = 0u;
    #pragma unroll
    for (int it = 0; it < 5; it++) {
        int r = wid + it * 8;
        const float4* rf4 = (const float4*)&s_in[r * PIN];
        float4 A = rf4[lane], B = rf4[lane + 1], C = rf4[lane + 2];
        float t[12] = {A.x,A.y,A.z,A.w, B.x,B.y,B.z,B.w, C.x,C.y,C.z,C.w};
        float S2 = fmaxf(t[2], t[3]);
        float S1 = fmaxf(t[1], S2);
        float S0 = fmaxf(t[0], S1);
        float P5  = fmaxf(t[4], t[5]);
        float P6  = fmaxf(P5, t[6]);
        float P7  = fmaxf(P6, t[7]);
        float P8  = fmaxf(P7, t[8]);
        float P9  = fmaxf(P8, t[9]);
        float P10 = fmaxf(P9, t[10]);
        float P11 = fmaxf(P10, t[11]);
        float4 o;
        o.x = fmaxf(S0,  P8);
        o.y = fmaxf(S1,  P9);
        o.z = fmaxf(S2,  P10);
        o.w = fmaxf(t[3], P11);
        ((float4*)&s_rm[r * PRM])[lane] = o;

        if (r >= HALO && r < HALO + TY) {
            #pragma unroll
            for (int j = 4; j < 8; j++) {
                float v = t[j];
                if (v >= 1.5f) myS++;
                unsigned int u = __float_as_uint(v);
                if (u - 0x3F800000u < 0x00400000u) {   /* v in [1.0,1.5) */
                    unsigned int p = atomicAdd(&s_wb[wid], 1u);
                    if (p < WCAP) s_band[wid * WCAP + p] = v;
                    else {
                        /* rare overflow: direct global + inline histogram */
                        unsigned int q = atomicAdd(&g_band_cnt[b], 1u);
                        if (q < NPB) g_band[b][q] = v;
                        atomicAdd(&s_c32[(fordu(v) >> 17) & 31u], 1u);
                    }
                }
            }
        }
    }
    #pragma unroll
    for (int o = 16; o; o >>= 1) myS += __shfl_xor_sync(0xFFFFFFFFu, myS, o);
    if (lane == 0) s_red[wid] = myS;
    __syncthreads();

    /* prefix over warp band counts; one global atomic for the whole block */
    if (tid == 0) {
        unsigned int acc = 0;
        #pragma unroll
        for (int w = 0; w < 8; w++) {
            unsigned int c = s_wb[w] < WCAP ? s_wb[w] : WCAP;
            s_pref8[w] = acc;
            acc += c;
        }
        s_bbase = atomicAdd(&g_band_cnt[b], acc);
        unsigned int s = 0;
        #pragma unroll
        for (int w = 0; w < 8; w++) s += s_red[w];
        if (s) atomicAdd(&g_cntS[b], s);
    }
    __syncthreads();

    /* each warp: flush own segment to global + histogram it (tiny) */
    {
        unsigned int cnt = s_wb[wid] < WCAP ? s_wb[wid] : WCAP;
        unsigned int gb0 = s_bbase + s_pref8[wid];
        for (unsigned int i = lane; i < cnt; i += 32) {
            float v = s_band[wid * WCAP + i];
            unsigned int q = gb0 + i;
            if (q < NPB) g_band[b][q] = v;
            atomicAdd(&s_c32[(fordu(v) >> 17) & 31u], 1u);
        }
    }
    __syncthreads();
    if (tid < 32) {
        unsigned int s = s_c32[tid];
        if (s) atomicAdd(&g_ctrC[b][tid], s);
    }
    __syncthreads();   /* s_u now free for candidates */

    /* -------- vpass: vHGW vertical 9-max + peak detect -------------------- */
    for (int c = tid; c < (TY / 8) * TX; c += 256) {
        int x  = c & 127;
        int yc = (c >> 7) << 3;
        float t[16];
        #pragma unroll
        for (int i = 0; i < 16; i++) t[i] = s_rm[(yc + i) * PRM + x];
        float S[8];
        S[7] = t[7];
        #pragma unroll
        for (int i = 6; i >= 0; i--) S[i] = fmaxf(t[i], S[i + 1]);
        float P[16];
        P[8] = t[8];
        #pragma unroll
        for (int i = 9; i < 16; i++) P[i] = fmaxf(P[i - 1], t[i]);
        #pragma unroll
        for (int j = 0; j < 8; j++) {
            float lm = fmaxf(S[j], P[j + 8]);
            float v  = s_in[(yc + j + HALO) * PIN + x + HALO];
            if (v == lm) {
                unsigned int idx = (unsigned)(ty0 + yc + j) * Wdim + (unsigned)(tx0 + x);
                unsigned long long key =
                    ((unsigned long long)fordu(v) << 32) | (unsigned long long)(0xFFFFFFFFu - idx);
                unsigned int p = atomicAdd(&s_ccnt, 1u);
                if (p < CBUF) s_cbuf[p] = key;
                else {
                    unsigned int q = atomicAdd(&g_cand_cnt[b], 1u);
                    if (q < CAND_CAP) g_cand[b][q] = key;
                }
            }
        }
    }
    __syncthreads();

    if (tid == 0) {
        unsigned int n = s_ccnt < CBUF ? s_ccnt : CBUF;
        s_cn = n;
        s_cbase = atomicAdd(&g_cand_cnt[b], n);
    }
    __syncthreads();
    for (unsigned int i = tid; i < s_cn; i += 256) {
        unsigned int q = s_cbase + i;
        if (q < CAND_CAP) g_cand[b][q] = s_cbuf[i];
    }
}

/* ------ K3: inline select + compact selected 15-bit bin from band --------- */
__global__ __launch_bounds__(256) void k3_compact() {
    __shared__ float s_buf[4096];
    __shared__ unsigned int s_cnt, s_base, s_n;
    __shared__ unsigned int s_sel;

    const int b = blockIdx.y;
    const int tid = threadIdx.x;

    if (tid == 0) {
        unsigned int rem;
        int sel = select32(b, &rem);
        s_sel = (sel < 0) ? 0xFFFFFFFFu : ((PRE_L2 << 5) | (unsigned)sel);
    }
    __syncthreads();
    const unsigned int selpre = s_sel;
    if (selpre == 0xFFFFFFFFu) return;    /* fallback handled in k45 */

    unsigned int n = g_band_cnt[b];
    if (n > NPB) n = NPB;
    const float4* s4 = (const float4*)g_band[b];

    for (unsigned int start = blockIdx.x * 4096u; start < n; start += 32u * 4096u) {
        if (tid == 0) s_cnt = 0u;
        __syncthreads();
        #pragma unroll
        for (int k = 0; k < 4; k++) {
            unsigned int i4 = start / 4u + tid + 256u * k;
            unsigned int e = i4 * 4u;
            if (e < n) {
                float4 v = s4[i4];
                float a[4] = {v.x, v.y, v.z, v.w};
                #pragma unroll
                for (int j = 0; j < 4; j++) {
                    if (e + j < n && (fordu(a[j]) >> 17) == selpre) {
                        unsigned int p = atomicAdd(&s_cnt, 1u);
                        s_buf[p] = a[j];
                    }
                }
            }
        }
        __syncthreads();
        if (tid == 0) {
            s_n = s_cnt;
            s_base = atomicAdd(&g_inbin_cnt[b], s_cnt);
        }
        __syncthreads();
        for (unsigned int i = tid; i < s_n; i += 256)
            g_inbin[b][s_base + i] = s_buf[i];
        __syncthreads();
    }
}

/* ------ K45: select/fallback + two-level refine + top-5 + output ---------- */
__global__ __launch_bounds__(512) void k45_final(const float* __restrict__ in,
                                                 float* __restrict__ out) {
    const int b = blockIdx.x;
    const int tid = threadIdx.x;
    const int lane = tid & 31;
    const int wrp  = tid >> 5;
    __shared__ unsigned int s_hist[4096];
    __shared__ unsigned int s_sum[256];
    __shared__ unsigned int s_pref[256];
    __shared__ unsigned int s_woff[8];
    __shared__ unsigned int s_selpre, s_shift, s_rank, s_cnt;
    __shared__ unsigned int s_sel2, s_rank2, s_thr;
    __shared__ unsigned long long s_w64[16];
    __shared__ unsigned long long s_top[TOPK];
    __shared__ unsigned long long s_amax;

    /* ----- phase 0: select from 32-bin counters ----- */
    if (tid == 0) {
        unsigned int rem;
        int sel = select32(b, &rem);
        if (sel >= 0) {
            s_shift  = 17u;
            s_selpre = (PRE_L2 << 5) | (unsigned)sel;
            s_rank   = rem;
            unsigned int c2 = g_inbin_cnt[b];
            s_cnt = c2 < NPB ? c2 : NPB;
        } else s_shift = 0u;
    }
    __syncthreads();

    if (s_shift == 0u) {
        /* ----- rare fallback: full hist + select + compact (this block) ---- */
        for (int i = tid; i < 4096; i += 512) s_hist[i] = 0u;
        __syncthreads();
        const float4* base4 = (const float4*)(in + (size_t)b * NPB);
        for (int j = 0; j < 512; j++) {
            float4 v = base4[tid + 512 * j];
            atomicAdd(&s_hist[fordu(v.x) >> 20], 1u);
            atomicAdd(&s_hist[fordu(v.y) >> 20], 1u);
            atomicAdd(&s_hist[fordu(v.z) >> 20], 1u);
            atomicAdd(&s_hist[fordu(v.w) >> 20], 1u);
        }
        __syncthreads();
        if (tid == 0) {
            unsigned int rem = (unsigned)KTHR;
            int bin = 4095;
            for (; bin > 0; bin--) {
                unsigned int c = s_hist[bin];
                if (rem <= c) break;
                rem -= c;
            }
            s_selpre = (unsigned)bin;
            s_shift  = 20u;
            s_rank   = rem;
            s_cnt    = 0u;
        }
        __syncthreads();
        const unsigned int selp = s_selpre;
        for (int j = 0; j < 512; j++) {
            float4 v = base4[tid + 512 * j];
            float a[4] = {v.x, v.y, v.z, v.w};
            #pragma unroll
            for (int q = 0; q < 4; q++) {
                if ((fordu(a[q]) >> 20) == selp) {
                    unsigned int p = atomicAdd(&s_cnt, 1u);
                    if (p < NPB) g_inbin[b][p] = a[q];
                }
            }
        }
        __syncthreads();
        if (tid == 0 && s_cnt > NPB) s_cnt = NPB;
        __syncthreads();
    }

    const unsigned int shift  = s_shift;
    const unsigned int selpre = s_selpre;
    const unsigned int rank   = s_rank;
    const unsigned int cnt    = s_cnt;
    const unsigned int lsh    = shift - 12u;
    const unsigned int lmask  = (1u << lsh) - 1u;

    /* ----- phase A1: 12-bit refine histogram ----- */
    for (int i = tid; i < 4096; i += 512) s_hist[i] = 0u;
    __syncthreads();
    for (unsigned int i = tid; i < cnt; i += 512) {
        unsigned int fo = fordu(g_inbin[b][i]);
        atomicAdd(&s_hist[(fo >> lsh) & 0xFFFu], 1u);
    }
    __syncthreads();

    /* parallel descending prefix over 256 chunks of 16 bins */
    if (tid < 256) {
        unsigned int s = 0;
        int hi = 4095 - 16 * tid;
        #pragma unroll
        for (int i = 0; i < 16; i++) s += s_hist[hi - i];
        s_sum[tid] = s;
        unsigned int wi = s;
        #pragma unroll
        for (int o = 1; o < 32; o <<= 1) {
            unsigned int u = __shfl_up_sync(0xFFFFFFFFu, wi, o);
            if (lane >= o) wi += u;
        }
        s_pref[tid] = wi;
        if (lane == 31) s_woff[tid >> 5] = wi;
    }
    __syncthreads();
    if (tid == 0) {
        unsigned int acc = 0;
        #pragma unroll
        for (int wq = 0; wq < 8; wq++) {
            unsigned int t = s_woff[wq];
            s_woff[wq] = acc;
            acc += t;
        }
    }
    __syncthreads();
    if (tid < 256) {
        unsigned int excl = s_pref[tid] - s_sum[tid] + s_woff[tid >> 5];
        if (excl < rank && rank <= excl + s_sum[tid]) {
            unsigned int rem = rank - excl;
            int hi2 = 4095 - 16 * tid;
            for (int i = 0; i < 16; i++) {
                unsigned int c = s_hist[hi2 - i];
                if (rem <= c) { s_sel2 = (unsigned)(hi2 - i); s_rank2 = rem; break; }
                rem -= c;
            }
        }
    }
    __syncthreads();
    const unsigned int sub = s_sel2, rank2 = s_rank2;
    __syncthreads();

    /* ----- phase A2: low-bit refine ----- */
    if (tid < 256) s_hist[tid] = 0u;
    __syncthreads();
    for (unsigned int i = tid; i < cnt; i += 512) {
        unsigned int fo = fordu(g_inbin[b][i]);
        if (((fo >> lsh) & 0xFFFu) == sub) atomicAdd(&s_hist[fo & lmask], 1u);
    }
    __syncthreads();
    if (tid == 0) {
        unsigned int rem = rank2;
        int bin = (int)lmask;
        for (; bin > 0; bin--) {
            unsigned int c = s_hist[bin];
            if (rem <= c) break;
            rem -= c;
        }
        s_thr = (selpre << shift) | (sub << lsh) | (unsigned)bin;
    }

    /* ----- phase B: top-5 + argmax over candidates ----- */
    unsigned int ccnt = g_cand_cnt[b];
    if (ccnt > CAND_CAP) ccnt = CAND_CAP;

    unsigned long long loc[TOPK];
    unsigned long long amax = 0ull;
    #pragma unroll
    for (int j = 0; j < TOPK; j++) loc[j] = 0ull;

    for (unsigned int bs = 0; bs < ccnt; bs += 4096) {
        unsigned long long kk[8];
        #pragma unroll
        for (int u = 0; u < 8; u++) {
            unsigned int i = bs + tid + 512u * u;
            kk[u] = (i < ccnt) ? g_cand[b][i] : 0ull;
        }
        #pragma unroll
        for (int u = 0; u < 8; u++) {
            amax = umax64(amax, kk[u]);
            if (kk[u] > loc[TOPK - 1]) {
                loc[TOPK - 1] = kk[u];
                #pragma unroll
                for (int j = TOPK - 1; j > 0; j--) {
                    if (loc[j] > loc[j - 1]) {
                        unsigned long long t = loc[j - 1]; loc[j - 1] = loc[j]; loc[j] = t;
                    }
                }
            }
        }
    }

    int ptr = 0;
    for (int r = 0; r < TOPK; r++) {
        unsigned long long cnd = (ptr < TOPK) ? loc[ptr] : 0ull;
        #pragma unroll
        for (int o = 16; o; o >>= 1)
            cnd = umax64(cnd, __shfl_xor_sync(0xFFFFFFFFu, cnd, o));
        if (lane == 0) s_w64[wrp] = cnd;
        __syncthreads();
        if (wrp == 0) {
            unsigned long long m = (lane < 16) ? s_w64[lane] : 0ull;
            #pragma unroll
            for (int o = 8; o; o >>= 1)
                m = umax64(m, __shfl_xor_sync(0xFFFFFFFFu, m, o));
            if (lane == 0) s_top[r] = m;
        }
        __syncthreads();
        unsigned long long wv = s_top[r];
        if (ptr < TOPK && loc[ptr] == wv && wv != 0ull) ptr++;
    }

    #pragma unroll
    for (int o = 16; o; o >>= 1)
        amax = umax64(amax, __shfl_xor_sync(0xFFFFFFFFu, amax, o));
    if (lane == 0) s_w64[wrp] = amax;
    __syncthreads();
    if (wrp == 0) {
        unsigned long long m = (lane < 16) ? s_w64[lane] : 0ull;
        #pragma unroll
        for (int o = 8; o; o >>= 1)
            m = umax64(m, __shfl_xor_sync(0xFFFFFFFFu, m, o));
        if (lane == 0) s_amax = m;
    }
    __syncthreads();

    /* ----- final assembly ----- */
    if (tid == 0) {
        const unsigned int thr_ord = s_thr;
        float topv[TOPK], xs[TOPK], ys[TOPK];
        bool hp[TOPK];
        #pragma unroll
        for (int j = 0; j < TOPK; j++) {
            unsigned long long k = s_top[j];
            hp[j] = (k != 0ull) && ((unsigned int)(k >> 32) > thr_ord);
            topv[j] = hp[j] ? fordu_inv((unsigned int)(k >> 32)) : NEG_INF;
            unsigned int idx = 0xFFFFFFFFu - (unsigned int)(k & 0xFFFFFFFFull);
            xs[j] = (float)(idx % Wdim);
            ys[j] = (float)(idx / Wdim);
        }
        bool has_any = hp[0];
        if (!has_any) {
            unsigned int fidx = 0xFFFFFFFFu - (unsigned int)(s_amax & 0xFFFFFFFFull);
            xs[0] = (float)(fidx % Wdim);
            ys[0] = (float)(fidx / Wdim);
        }
        float peak_max = topv[0];
        int n_valid = 0;
        #pragma unroll
        for (int j = 0; j < TOPK; j++)
            if (topv[j] >= peak_max * 0.5f && hp[j]) n_valid++;
        if (n_valid < 1) n_valid = 1;
        #pragma unroll
        for (int j = 0; j < TOPK; j++) {
            bool keep = (j < n_valid);
            out[b * (TOPK * 2) + 2 * j + 0] = keep ? xs[j] : -1.0f;
            out[b * (TOPK * 2) + 2 * j + 1] = keep ? ys[j] : -1.0f;
            out[BATCH * TOPK * 2 + b * TOPK + j] = keep ? 1.0f : -1.0f;
        }
    }

    /* ----- re-zero this batch's state for next replay ----- */
    __syncthreads();
    if (tid == 0) {
        g_cand_cnt[b]  = 0u;
        g_band_cnt[b]  = 0u;
        g_cntS[b]      = 0u;
        g_inbin_cnt[b] = 0u;
    }
    if (tid < 32) g_ctrC[b][tid] = 0u;
}

/* -------------------------------- launch ---------------------------------- */
extern "C" void kernel_launch(void* const* d_in, const int* in_sizes, int n_in,
                              void* d_out, int out_size) {
    const float* in = (const float*)d_in[0];
    float* out = (float*)d_out;
    (void)in_sizes; (void)n_in; (void)out_size;

    k1_main<<<dim3(Wdim / TX, Hdim / TY, BATCH), 256>>>(in);
    k3_compact<<<dim3(32, BATCH), 256>>>();
    k45_final<<<BATCH, 512>>>(in, out);
}

// round 11
// speedup vs baseline: 1.4592x; 1.4592x over previous
#include <cuda_runtime.h>
#include <stdint.h>

#define BATCH 16
#define Hdim 1024
#define Wdim 1024
#define NPB (Hdim*Wdim)
#define KTHR 104857
#define TOPK 5
#define CAND_CAP 65536

#define TX 128
#define TY 32
#define HALO 4
#define INW (TX + 2*HALO)    /* 136 */
#define INH (TY + 2*HALO)    /* 40  */
#define PIN 136
#define PRM 128
#define CBUF 256
#define BANDBUF 512

#define PRE_L2 766u            /* (fordu(v)>>22) for v in [1.0,1.5) */

/* ------------ scratch (zero-init at load; re-zeroed every run) ------------ */
__device__ unsigned long long g_cand[BATCH][CAND_CAP];
__device__ unsigned int       g_cand_cnt[BATCH];
__device__ unsigned int       g_cntS[BATCH];
__device__ unsigned int       g_ctrC[BATCH][32];
__device__ float              g_band[BATCH][NPB];
__device__ unsigned int       g_band_cnt[BATCH];
__device__ float              g_inbin[BATCH][NPB];
__device__ unsigned int       g_inbin_cnt[BATCH];

__device__ __forceinline__ unsigned int fordu(float f) {
    unsigned int u = __float_as_uint(f);
    return u ^ (unsigned int)(((int)u >> 31) | (int)0x80000000);
}
__device__ __forceinline__ float fordu_inv(unsigned int v) {
    unsigned int u = (v & 0x80000000u) ? (v ^ 0x80000000u) : ~v;
    return __uint_as_float(u);
}
__device__ __forceinline__ unsigned long long umax64(unsigned long long a, unsigned long long b) {
    return a > b ? a : b;
}
#define NEG_INF __int_as_float(0xff800000)

/* 32-bin quantile select: returns sel or -1 */
__device__ __forceinline__ int select32(int b, unsigned int* remOut) {
    unsigned int cum = g_cntS[b];
    for (int j = 31; j >= 0; j--) {
        unsigned int c = g_ctrC[b][j];
        if (cum < (unsigned)KTHR && (unsigned)KTHR <= cum + c) {
            *remOut = (unsigned)KTHR - cum;
            return j;
        }
        cum += c;
    }
    return -1;
}

/* --------- K1: max filter + counting + band collect + peak candidates ----- */
__global__ __launch_bounds__(256) void k1_main(const float* __restrict__ in) {
    __shared__ __align__(16) float s_in[INH * PIN];
    __shared__ __align__(16) float s_rm[INH * PRM];
    __shared__ __align__(16) char  s_u[BANDBUF * 4 > CBUF * 8 ? BANDBUF * 4 : CBUF * 8];
    __shared__ unsigned int s_ccnt, s_cbase, s_cn;
    __shared__ unsigned int s_bcnt, s_bbase, s_bn;
    __shared__ unsigned int s_c32[32];
    __shared__ unsigned int s_red[8];

    float* s_band = (float*)s_u;
    unsigned long long* s_cbuf = (unsigned long long*)s_u;

    const int b   = blockIdx.z;
    const int tx0 = blockIdx.x * TX;
    const int ty0 = blockIdx.y * TY;
    const float* base = in + (size_t)b * NPB;
    const int tid  = threadIdx.x;
    const int lane = tid & 31;
    const int wid  = tid >> 5;

    if (tid == 0) { s_ccnt = 0u; s_bcnt = 0u; }
    if (tid < 32) s_c32[tid] = 0u;

    /* ---------------- load tile + halo ---------------- */
    const bool interior = (blockIdx.x > 0) && (blockIdx.x < (Wdim/TX - 1)) &&
                          (blockIdx.y > 0) && (blockIdx.y < (Hdim/TY - 1));
    if (interior) {
        const float4* gbase = (const float4*)(base + (size_t)(ty0 - HALO) * Wdim + (tx0 - HALO));
        #pragma unroll
        for (int ri = 0; ri < 5; ri++) {
            int r = wid + ri * 8;
            const float4* grow = gbase + (size_t)r * (Wdim / 4);
            float4* srow = (float4*)&s_in[r * PIN];
            srow[lane] = grow[lane];
            if (lane < 2) srow[32 + lane] = grow[32 + lane];
        }
    } else {
        #pragma unroll
        for (int ri = 0; ri < 5; ri++) {
            int r = wid + ri * 8;
            int gy = ty0 + r - HALO;
            bool rowin = (unsigned)gy < (unsigned)Hdim;
            #pragma unroll
            for (int ci = 0; ci < 5; ci++) {
                int c = lane + ci * 32;
                if (c < INW) {
                    int gx = tx0 + c - HALO;
                    float v = NEG_INF;
                    if (rowin && (unsigned)gx < (unsigned)Wdim) v = base[gy * Wdim + gx];
                    s_in[r * PIN + c] = v;
                }
            }
        }
    }
    __syncthreads();

    /* -------- hpass: warp-per-row vHGW 9-max + lean tests ----------------- */
    unsigned int myS = 0u;
    #pragma unroll
    for (int it = 0; it < 5; it++) {
        int r = wid + it * 8;
        const float4* rf4 = (const float4*)&s_in[r * PIN];
        float4 A = rf4[lane], B = rf4[lane + 1], C = rf4[lane + 2];
        float t[12] = {A.x,A.y,A.z,A.w, B.x,B.y,B.z,B.w, C.x,C.y,C.z,C.w};
        float S2 = fmaxf(t[2], t[3]);
        float S1 = fmaxf(t[1], S2);
        float S0 = fmaxf(t[0], S1);
        float P5  = fmaxf(t[4], t[5]);
        float P6  = fmaxf(P5, t[6]);
        float P7  = fmaxf(P6, t[7]);
        float P8  = fmaxf(P7, t[8]);
        float P9  = fmaxf(P8, t[9]);
        float P10 = fmaxf(P9, t[10]);
        float P11 = fmaxf(P10, t[11]);
        float4 o;
        o.x = fmaxf(S0,  P8);
        o.y = fmaxf(S1,  P9);
        o.z = fmaxf(S2,  P10);
        o.w = fmaxf(t[3], P11);
        ((float4*)&s_rm[r * PRM])[lane] = o;

        if (r >= HALO && r < HALO + TY) {
            #pragma unroll
            for (int j = 4; j < 8; j++) {
                float v = t[j];
                if (v >= 1.5f) myS++;
                if (__float_as_uint(v) - 0x3F800000u < 0x00400000u) { /* [1.0,1.5) */
                    unsigned int p = atomicAdd(&s_bcnt, 1u);
                    if (p < BANDBUF) s_band[p] = v;
                    else {
                        /* rare overflow: direct global + inline histogram */
                        unsigned int q = atomicAdd(&g_band_cnt[b], 1u);
                        if (q < NPB) g_band[b][q] = v;
                        atomicAdd(&s_c32[(fordu(v) >> 17) & 31u], 1u);
                    }
                }
            }
        }
    }
    #pragma unroll
    for (int o = 16; o; o >>= 1) myS += __shfl_xor_sync(0xFFFFFFFFu, myS, o);
    if (lane == 0) s_red[wid] = myS;
    __syncthreads();

    /* flush counters + band buffer (coalesced) + deferred histogram ------- */
    if (tid == 0) {
        unsigned int s = 0;
        #pragma unroll
        for (int w = 0; w < 8; w++) s += s_red[w];
        if (s) atomicAdd(&g_cntS[b], s);
        unsigned int m = s_bcnt < BANDBUF ? s_bcnt : BANDBUF;
        s_bn = m;
        s_bbase = atomicAdd(&g_band_cnt[b], m);
    }
    __syncthreads();
    for (unsigned int i = tid; i < s_bn; i += 256) {
        float v = s_band[i];
        unsigned int q = s_bbase + i;
        if (q < NPB) g_band[b][q] = v;
        atomicAdd(&s_c32[(fordu(v) >> 17) & 31u], 1u);
    }
    __syncthreads();
    if (tid < 32) {
        unsigned int s = s_c32[tid];
        if (s) atomicAdd(&g_ctrC[b][tid], s);
    }
    __syncthreads();   /* band flushed; s_u now free for candidates */

    /* -------- vpass: vHGW vertical 9-max + peak detect -------------------- */
    for (int c = tid; c < (TY / 8) * TX; c += 256) {
        int x  = c & 127;
        int yc = (c >> 7) << 3;
        float t[16];
        #pragma unroll
        for (int i = 0; i < 16; i++) t[i] = s_rm[(yc + i) * PRM + x];
        float S[8];
        S[7] = t[7];
        #pragma unroll
        for (int i = 6; i >= 0; i--) S[i] = fmaxf(t[i], S[i + 1]);
        float P[16];
        P[8] = t[8];
        #pragma unroll
        for (int i = 9; i < 16; i++) P[i] = fmaxf(P[i - 1], t[i]);
        #pragma unroll
        for (int j = 0; j < 8; j++) {
            float lm = fmaxf(S[j], P[j + 8]);
            float v  = s_in[(yc + j + HALO) * PIN + x + HALO];
            if (v == lm) {
                unsigned int idx = (unsigned)(ty0 + yc + j) * Wdim + (unsigned)(tx0 + x);
                unsigned long long key =
                    ((unsigned long long)fordu(v) << 32) | (unsigned long long)(0xFFFFFFFFu - idx);
                unsigned int p = atomicAdd(&s_ccnt, 1u);
                if (p < CBUF) s_cbuf[p] = key;
                else {
                    unsigned int q = atomicAdd(&g_cand_cnt[b], 1u);
                    if (q < CAND_CAP) g_cand[b][q] = key;
                }
            }
        }
    }
    __syncthreads();

    if (tid == 0) {
        unsigned int n = s_ccnt < CBUF ? s_ccnt : CBUF;
        s_cn = n;
        s_cbase = atomicAdd(&g_cand_cnt[b], n);
    }
    __syncthreads();
    for (unsigned int i = tid; i < s_cn; i += 256) {
        unsigned int q = s_cbase + i;
        if (q < CAND_CAP) g_cand[b][q] = s_cbuf[i];
    }
}

/* ------ K3: inline select + compact selected 15-bit bin from band --------- */
__global__ __launch_bounds__(256) void k3_compact() {
    __shared__ float s_buf[4096];
    __shared__ unsigned int s_cnt, s_base, s_n;
    __shared__ unsigned int s_sel;

    const int b = blockIdx.y;
    const int tid = threadIdx.x;

    if (tid == 0) {
        unsigned int rem;
        int sel = select32(b, &rem);
        s_sel = (sel < 0) ? 0xFFFFFFFFu : ((PRE_L2 << 5) | (unsigned)sel);
    }
    __syncthreads();
    const unsigned int selpre = s_sel;
    if (selpre == 0xFFFFFFFFu) return;    /* fallback handled in k45 */

    unsigned int n = g_band_cnt[b];
    if (n > NPB) n = NPB;
    const float4* s4 = (const float4*)g_band[b];

    for (unsigned int start = blockIdx.x * 4096u; start < n; start += 32u * 4096u) {
        if (tid == 0) s_cnt = 0u;
        __syncthreads();
        #pragma unroll
        for (int k = 0; k < 4; k++) {
            unsigned int i4 = start / 4u + tid + 256u * k;
            unsigned int e = i4 * 4u;
            if (e < n) {
                float4 v = s4[i4];
                float a[4] = {v.x, v.y, v.z, v.w};
                #pragma unroll
                for (int j = 0; j < 4; j++) {
                    if (e + j < n && (fordu(a[j]) >> 17) == selpre) {
                        unsigned int p = atomicAdd(&s_cnt, 1u);
                        s_buf[p] = a[j];
                    }
                }
            }
        }
        __syncthreads();
        if (tid == 0) {
            s_n = s_cnt;
            s_base = atomicAdd(&g_inbin_cnt[b], s_cnt);
        }
        __syncthreads();
        for (unsigned int i = tid; i < s_n; i += 256)
            g_inbin[b][s_base + i] = s_buf[i];
        __syncthreads();
    }
}

/* ------ K45: select/fallback + two-level refine + top-5 + output ---------- */
__global__ __launch_bounds__(512) void k45_final(const float* __restrict__ in,
                                                 float* __restrict__ out) {
    const int b = blockIdx.x;
    const int tid = threadIdx.x;
    const int lane = tid & 31;
    const int wrp  = tid >> 5;
    __shared__ unsigned int s_hist[4096];
    __shared__ unsigned int s_sum[256];
    __shared__ unsigned int s_pref[256];
    __shared__ unsigned int s_woff[8];
    __shared__ unsigned int s_selpre, s_shift, s_rank, s_cnt;
    __shared__ unsigned int s_sel2, s_rank2, s_thr;
    __shared__ unsigned long long s_w64[16];
    __shared__ unsigned long long s_top[TOPK];
    __shared__ unsigned long long s_amax;

    /* ----- phase 0: select from 32-bin counters ----- */
    if (tid == 0) {
        unsigned int rem;
        int sel = select32(b, &rem);
        if (sel >= 0) {
            s_shift  = 17u;
            s_selpre = (PRE_L2 << 5) | (unsigned)sel;
            s_rank   = rem;
            unsigned int c2 = g_inbin_cnt[b];
            s_cnt = c2 < NPB ? c2 : NPB;
        } else s_shift = 0u;
    }
    __syncthreads();

    if (s_shift == 0u) {
        /* ----- rare fallback: full hist + select + compact (this block) ---- */
        for (int i = tid; i < 4096; i += 512) s_hist[i] = 0u;
        __syncthreads();
        const float4* base4 = (const float4*)(in + (size_t)b * NPB);
        for (int j = 0; j < 512; j++) {
            float4 v = base4[tid + 512 * j];
            atomicAdd(&s_hist[fordu(v.x) >> 20], 1u);
            atomicAdd(&s_hist[fordu(v.y) >> 20], 1u);
            atomicAdd(&s_hist[fordu(v.z) >> 20], 1u);
            atomicAdd(&s_hist[fordu(v.w) >> 20], 1u);
        }
        __syncthreads();
        if (tid == 0) {
            unsigned int rem = (unsigned)KTHR;
            int bin = 4095;
            for (; bin > 0; bin--) {
                unsigned int c = s_hist[bin];
                if (rem <= c) break;
                rem -= c;
            }
            s_selpre = (unsigned)bin;
            s_shift  = 20u;
            s_rank   = rem;
            s_cnt    = 0u;
        }
        __syncthreads();
        const unsigned int selp = s_selpre;
        for (int j = 0; j < 512; j++) {
            float4 v = base4[tid + 512 * j];
            float a[4] = {v.x, v.y, v.z, v.w};
            #pragma unroll
            for (int q = 0; q < 4; q++) {
                if ((fordu(a[q]) >> 20) == selp) {
                    unsigned int p = atomicAdd(&s_cnt, 1u);
                    if (p < NPB) g_inbin[b][p] = a[q];
                }
            }
        }
        __syncthreads();
        if (tid == 0 && s_cnt > NPB) s_cnt = NPB;
        __syncthreads();
    }

    const unsigned int shift  = s_shift;
    const unsigned int selpre = s_selpre;
    const unsigned int rank   = s_rank;
    const unsigned int cnt    = s_cnt;
    const unsigned int lsh    = shift - 12u;
    const unsigned int lmask  = (1u << lsh) - 1u;

    /* ----- phase A1: 12-bit refine histogram ----- */
    for (int i = tid; i < 4096; i += 512) s_hist[i] = 0u;
    __syncthreads();
    for (unsigned int i = tid; i < cnt; i += 512) {
        unsigned int fo = fordu(g_inbin[b][i]);
        atomicAdd(&s_hist[(fo >> lsh) & 0xFFFu], 1u);
    }
    __syncthreads();

    /* parallel descending prefix over 256 chunks of 16 bins */
    if (tid < 256) {
        unsigned int s = 0;
        int hi = 4095 - 16 * tid;
        #pragma unroll
        for (int i = 0; i < 16; i++) s += s_hist[hi - i];
        s_sum[tid] = s;
        unsigned int wi = s;
        #pragma unroll
        for (int o = 1; o < 32; o <<= 1) {
            unsigned int u = __shfl_up_sync(0xFFFFFFFFu, wi, o);
            if (lane >= o) wi += u;
        }
        s_pref[tid] = wi;
        if (lane == 31) s_woff[tid >> 5] = wi;
    }
    __syncthreads();
    if (tid == 0) {
        unsigned int acc = 0;
        #pragma unroll
        for (int wq = 0; wq < 8; wq++) {
            unsigned int t = s_woff[wq];
            s_woff[wq] = acc;
            acc += t;
        }
    }
    __syncthreads();
    if (tid < 256) {
        unsigned int excl = s_pref[tid] - s_sum[tid] + s_woff[tid >> 5];
        if (excl < rank && rank <= excl + s_sum[tid]) {
            unsigned int rem = rank - excl;
            int hi2 = 4095 - 16 * tid;
            for (int i = 0; i < 16; i++) {
                unsigned int c = s_hist[hi2 - i];
                if (rem <= c) { s_sel2 = (unsigned)(hi2 - i); s_rank2 = rem; break; }
                rem -= c;
            }
        }
    }
    __syncthreads();
    const unsigned int sub = s_sel2, rank2 = s_rank2;
    __syncthreads();

    /* ----- phase A2: low-bit refine ----- */
    if (tid < 256) s_hist[tid] = 0u;
    __syncthreads();
    for (unsigned int i = tid; i < cnt; i += 512) {
        unsigned int fo = fordu(g_inbin[b][i]);
        if (((fo >> lsh) & 0xFFFu) == sub) atomicAdd(&s_hist[fo & lmask], 1u);
    }
    __syncthreads();
    if (tid == 0) {
        unsigned int rem = rank2;
        int bin = (int)lmask;
        for (; bin > 0; bin--) {
            unsigned int c = s_hist[bin];
            if (rem <= c) break;
            rem -= c;
        }
        s_thr = (selpre << shift) | (sub << lsh) | (unsigned)bin;
    }

    /* ----- phase B: top-5 + argmax over candidates ----- */
    unsigned int ccnt = g_cand_cnt[b];
    if (ccnt > CAND_CAP) ccnt = CAND_CAP;

    unsigned long long loc[TOPK];
    unsigned long long amax = 0ull;
    #pragma unroll
    for (int j = 0; j < TOPK; j++) loc[j] = 0ull;

    for (unsigned int bs = 0; bs < ccnt; bs += 4096) {
        unsigned long long kk[8];
        #pragma unroll
        for (int u = 0; u < 8; u++) {
            unsigned int i = bs + tid + 512u * u;
            kk[u] = (i < ccnt) ? g_cand[b][i] : 0ull;
        }
        #pragma unroll
        for (int u = 0; u < 8; u++) {
            amax = umax64(amax, kk[u]);
            if (kk[u] > loc[TOPK - 1]) {
                loc[TOPK - 1] = kk[u];
                #pragma unroll
                for (int j = TOPK - 1; j > 0; j--) {
                    if (loc[j] > loc[j - 1]) {
                        unsigned long long t = loc[j - 1]; loc[j - 1] = loc[j]; loc[j] = t;
                    }
                }
            }
        }
    }

    int ptr = 0;
    for (int r = 0; r < TOPK; r++) {
        unsigned long long cnd = (ptr < TOPK) ? loc[ptr] : 0ull;
        #pragma unroll
        for (int o = 16; o; o >>= 1)
            cnd = umax64(cnd, __shfl_xor_sync(0xFFFFFFFFu, cnd, o));
        if (lane == 0) s_w64[wrp] = cnd;
        __syncthreads();
        if (wrp == 0) {
            unsigned long long m = (lane < 16) ? s_w64[lane] : 0ull;
            #pragma unroll
            for (int o = 8; o; o >>= 1)
                m = umax64(m, __shfl_xor_sync(0xFFFFFFFFu, m, o));
            if (lane == 0) s_top[r] = m;
        }
        __syncthreads();
        unsigned long long wv = s_top[r];
        if (ptr < TOPK && loc[ptr] == wv && wv != 0ull) ptr++;
    }

    #pragma unroll
    for (int o = 16; o; o >>= 1)
        amax = umax64(amax, __shfl_xor_sync(0xFFFFFFFFu, amax, o));
    if (lane == 0) s_w64[wrp] = amax;
    __syncthreads();
    if (wrp == 0) {
        unsigned long long m = (lane < 16) ? s_w64[lane] : 0ull;
        #pragma unroll
        for (int o = 8; o; o >>= 1)
            m = umax64(m, __shfl_xor_sync(0xFFFFFFFFu, m, o));
        if (lane == 0) s_amax = m;
    }
    __syncthreads();

    /* ----- final assembly ----- */
    if (tid == 0) {
        const unsigned int thr_ord = s_thr;
        float topv[TOPK], xs[TOPK], ys[TOPK];
        bool hp[TOPK];
        #pragma unroll
        for (int j = 0; j < TOPK; j++) {
            unsigned long long k = s_top[j];
            hp[j] = (k != 0ull) && ((unsigned int)(k >> 32) > thr_ord);
            topv[j] = hp[j] ? fordu_inv((unsigned int)(k >> 32)) : NEG_INF;
            unsigned int idx = 0xFFFFFFFFu - (unsigned int)(k & 0xFFFFFFFFull);
            xs[j] = (float)(idx % Wdim);
            ys[j] = (float)(idx / Wdim);
        }
        bool has_any = hp[0];
        if (!has_any) {
            unsigned int fidx = 0xFFFFFFFFu - (unsigned int)(s_amax & 0xFFFFFFFFull);
            xs[0] = (float)(fidx % Wdim);
            ys[0] = (float)(fidx / Wdim);
        }
        float peak_max = topv[0];
        int n_valid = 0;
        #pragma unroll
        for (int j = 0; j < TOPK; j++)
            if (topv[j] >= peak_max * 0.5f && hp[j]) n_valid++;
        if (n_valid < 1) n_valid = 1;
        #pragma unroll
        for (int j = 0; j < TOPK; j++) {
            bool keep = (j < n_valid);
            out[b * (TOPK * 2) + 2 * j + 0] = keep ? xs[j] : -1.0f;
            out[b * (TOPK * 2) + 2 * j + 1] = keep ? ys[j] : -1.0f;
            out[BATCH * TOPK * 2 + b * TOPK + j] = keep ? 1.0f : -1.0f;
        }
    }

    /* ----- re-zero this batch's state for next replay ----- */
    __syncthreads();
    if (tid == 0) {
        g_cand_cnt[b]  = 0u;
        g_band_cnt[b]  = 0u;
        g_cntS[b]      = 0u;
        g_inbin_cnt[b] = 0u;
    }
    if (tid < 32) g_ctrC[b][tid] = 0u;
}

/* -------------------------------- launch ---------------------------------- */
extern "C" void kernel_launch(void* const* d_in, const int* in_sizes, int n_in,
                              void* d_out, int out_size) {
    const float* in = (const float*)d_in[0];
    float* out = (float*)d_out;
    (void)in_sizes; (void)n_in; (void)out_size;

    k1_main<<<dim3(Wdim / TX, Hdim / TY, BATCH), 256>>>(in);
    k3_compact<<<dim3(32, BATCH), 256>>>();
    k45_final<<<BATCH, 512>>>(in, out);
}